// round 12
// baseline (speedup 1.0000x reference)
#include <cuda_runtime.h>
#include <cstdint>

#define NB 4
#define LL 4096
#define HH 16
#define DD 64
#define MM 64
#define CC 128
#define GG 32
#define NTILE (NB*GG*HH)   // 2048
#define EPS 1e-6f

// strides (floats)
#define SB 72    // unified stride: works for row-pattern (gid*8+tg) and col-pattern banks
#define SSW 132  // S tile stride

__device__ float g_kv [NTILE*DD*MM];
__device__ float g_kvp[NTILE*DD*MM];
__device__ float g_ks [NTILE*DD];
__device__ float g_ksp[NTILE*DD];

__device__ __forceinline__ float phi(float x) { return x > 0.f ? x + 1.f : __expf(x); }
__device__ __forceinline__ float f2tf(float f) {
    uint32_t r; asm("cvt.rna.tf32.f32 %0, %1;" : "=r"(r) : "f"(f)); return __uint_as_float(r);
}
__device__ __forceinline__ void mma8(float c[4], uint32_t a0, uint32_t a1, uint32_t a2, uint32_t a3,
                                     uint32_t b0, uint32_t b1) {
    asm volatile("mma.sync.aligned.m16n8k8.row.col.f32.tf32.tf32.f32 "
                 "{%0,%1,%2,%3},{%4,%5,%6,%7},{%8,%9},{%0,%1,%2,%3};"
                 : "+f"(c[0]), "+f"(c[1]), "+f"(c[2]), "+f"(c[3])
                 : "r"(a0), "r"(a1), "r"(a2), "r"(a3), "r"(b0), "r"(b1));
}

// ---------------------------------------------------------------------------
// k_state: unchanged (best measured config: 256 thr, 16x32 tiles, 3 CTAs/SM)
// ---------------------------------------------------------------------------
#define SMEM1 ((2*CC*SB + 256) * 4)

__global__ __launch_bounds__(256, 3)
void k_state(const float* __restrict__ K, const float* __restrict__ V) {
    extern __shared__ float sm[];
    float* sk   = sm;
    float* sv   = sm + CC * SB;
    float* sred = sm + 2 * CC * SB;
    const int tid = threadIdx.x, wid = tid >> 5, lane = tid & 31;
    const int gid = lane >> 2, tg = lane & 3;
    const int b = blockIdx.x, h = b & 15, g = (b >> 4) & 31, n = b >> 9;

    #pragma unroll
    for (int it = 0; it < 8; it++) {
        int idx = tid + it * 256;
        int r = idx >> 4, c0 = (idx & 15) * 4;
        int gb = ((n * LL + g * CC + r) * HH + h) * DD + c0;
        float4 k4 = *(const float4*)(K + gb);
        float4 v4 = *(const float4*)(V + gb);
        sk[r * SB + c0 + 0] = f2tf(phi(k4.x));
        sk[r * SB + c0 + 1] = f2tf(phi(k4.y));
        sk[r * SB + c0 + 2] = f2tf(phi(k4.z));
        sk[r * SB + c0 + 3] = f2tf(phi(k4.w));
        sv[r * SB + c0 + 0] = f2tf(v4.x);
        sv[r * SB + c0 + 1] = f2tf(v4.y);
        sv[r * SB + c0 + 2] = f2tf(v4.z);
        sv[r * SB + c0 + 3] = f2tf(v4.w);
    }
    __syncthreads();

    {
        int d = tid & 63, part = tid >> 6;
        float s = 0.f;
        #pragma unroll 8
        for (int c = part * 32; c < part * 32 + 32; c++) s += sk[c * SB + d];
        sred[part * 64 + d] = s;
    }

    const int d0 = (wid >> 1) * 16, oc = (wid & 1) * 32;
    float cD[4][4];
    #pragma unroll
    for (int nj = 0; nj < 4; nj++)
        #pragma unroll
        for (int q = 0; q < 4; q++) cD[nj][q] = 0.f;

    #pragma unroll
    for (int kk = 0; kk < 16; kk++) {
        int kr = kk * 8 + tg;
        uint32_t a0 = __float_as_uint(sk[kr * SB + d0 + gid]);
        uint32_t a1 = __float_as_uint(sk[kr * SB + d0 + 8 + gid]);
        uint32_t a2 = __float_as_uint(sk[(kr + 4) * SB + d0 + gid]);
        uint32_t a3 = __float_as_uint(sk[(kr + 4) * SB + d0 + 8 + gid]);
        #pragma unroll
        for (int nj = 0; nj < 4; nj++) {
            uint32_t b0 = __float_as_uint(sv[kr * SB + oc + nj * 8 + gid]);
            uint32_t b1 = __float_as_uint(sv[(kr + 4) * SB + oc + nj * 8 + gid]);
            mma8(cD[nj], a0, a1, a2, a3, b0, b1);
        }
    }

    float* dst = g_kv + (size_t)b * (DD * MM);
    #pragma unroll
    for (int nj = 0; nj < 4; nj++) {
        int col = oc + nj * 8 + 2 * tg;
        *(float2*)(dst + (d0 + gid) * MM + col)     = make_float2(cD[nj][0], cD[nj][1]);
        *(float2*)(dst + (d0 + 8 + gid) * MM + col) = make_float2(cD[nj][2], cD[nj][3]);
    }

    __syncthreads();
    if (tid < 64)
        g_ks[(size_t)b * DD + tid] = sred[tid] + sred[64 + tid] + sred[128 + tid] + sred[192 + tid];
}

// ---------------------------------------------------------------------------
// k_scan: unchanged R5 version. grid (64,4)x256.
// ---------------------------------------------------------------------------
__global__ __launch_bounds__(256, 4)
void k_scan() {
    const int nh = blockIdx.x, n = nh >> 4, h = nh & 15;
    const int pos = blockIdx.y * 1024 + threadIdx.x * 4;
    float4 acc = make_float4(0.f, 0.f, 0.f, 0.f);
    size_t base0 = ((size_t)(n * GG * HH + h)) * (DD * MM) + pos;
    float4 nxt = *(const float4*)&g_kv[base0];
    for (int g = 0; g < GG; g++) {
        float4 cur = nxt;
        size_t base = ((size_t)((n * GG + g) * HH + h)) * (DD * MM) + pos;
        if (g + 1 < GG) {
            size_t basen = ((size_t)((n * GG + g + 1) * HH + h)) * (DD * MM) + pos;
            nxt = *(const float4*)&g_kv[basen];
        }
        *(float4*)&g_kvp[base] = acc;
        acc.x += cur.x; acc.y += cur.y; acc.z += cur.z; acc.w += cur.w;
    }
    if (blockIdx.y == 0 && threadIdx.x < DD) {
        float a = 0.f;
        for (int g = 0; g < GG; g++) {
            size_t off = (size_t)((n * GG + g) * HH + h) * DD + threadIdx.x;
            g_ksp[off] = a;
            a += g_ks[off];
        }
    }
}

// ---------------------------------------------------------------------------
// k_main: causal row-split. grid = NTILE*2 (upper half = rows 0-63, lower = 64-127).
// 256 threads, 2 CTAs/SM. K buffer reused for V (V prefetched to registers).
// ---------------------------------------------------------------------------
#define OFF_SQ   0                       // 64 x SB
#define OFF_KV   (64*SB)                 // 128 x SB (K, then V)
#define OFF_SS   (OFF_KV + 128*SB)       // 64 x SSW
#define OFF_KVP  (OFF_SS + 64*SSW)       // 64 x SB
#define OFF_KSP  (OFF_KVP + 64*SB)       // 64
#define OFF_ZP   (OFF_KSP + 64)          // [4][64]
#define OFF_Z    (OFF_ZP + 256)          // 64
#define SM3_FLOATS (OFF_Z + 64)
#define SMEM3  (SM3_FLOATS * 4)          // 109056 bytes

__global__ __launch_bounds__(256, 2)
void k_main(const float* __restrict__ Q, const float* __restrict__ K,
            const float* __restrict__ V, float* __restrict__ O) {
    extern __shared__ float sm[];
    float* sq   = sm + OFF_SQ;
    float* skv  = sm + OFF_KV;
    float* sS   = sm + OFF_SS;
    float* skvp = sm + OFF_KVP;
    float* sksp = sm + OFF_KSP;
    float* szp  = sm + OFF_ZP;
    float* sz   = sm + OFF_Z;

    const int tid = threadIdx.x, wid = tid >> 5, lane = tid & 31;
    const int gid = lane >> 2, tg = lane & 3;
    const int bx = blockIdx.x;
    const int b = bx >> 1, half = bx & 1;
    const int h = b & 15, g = (b >> 4) & 31, n = b >> 9;
    const int kmax = half ? 128 : 64;      // K/V rows this CTA needs
    const int nk4it = kmax >> 4;           // iterations of 256-thread f4 loop (4 or 8)

    szp[tid] = 0.f;                        // zero rowsum partials (256 entries)

    // ---- global loads: Q (64 rows), K (kmax rows) to smem; V (kmax rows) to regs ----
    #pragma unroll
    for (int it = 0; it < 4; it++) {
        int idx = tid + it * 256;          // 0..1023
        int r = idx >> 4, c0 = (idx & 15) * 4;
        int gb = ((n * LL + g * CC + half * 64 + r) * HH + h) * DD + c0;
        float4 q4 = *(const float4*)(Q + gb);
        sq[r * SB + c0 + 0] = f2tf(phi(q4.x));
        sq[r * SB + c0 + 1] = f2tf(phi(q4.y));
        sq[r * SB + c0 + 2] = f2tf(phi(q4.z));
        sq[r * SB + c0 + 3] = f2tf(phi(q4.w));
    }
    float4 vreg[8];
    #pragma unroll
    for (int it = 0; it < 8; it++) {
        if (it < nk4it) {
            int idx = tid + it * 256;
            int r = idx >> 4, c0 = (idx & 15) * 4;
            int gb = ((n * LL + g * CC + r) * HH + h) * DD + c0;
            float4 k4 = *(const float4*)(K + gb);
            vreg[it] = *(const float4*)(V + gb);
            skv[r * SB + c0 + 0] = f2tf(phi(k4.x));
            skv[r * SB + c0 + 1] = f2tf(phi(k4.y));
            skv[r * SB + c0 + 2] = f2tf(phi(k4.z));
            skv[r * SB + c0 + 3] = f2tf(phi(k4.w));
        }
    }
    {
        const float* src = g_kvp + (size_t)b * (DD * MM);
        #pragma unroll
        for (int it = 0; it < 4; it++) {
            int idx = tid + it * 256;
            int d = idx >> 4, m0 = (idx & 15) * 4;
            float4 s4 = *(const float4*)(src + d * MM + m0);
            skvp[d * SB + m0 + 0] = f2tf(s4.x);
            skvp[d * SB + m0 + 1] = f2tf(s4.y);
            skvp[d * SB + m0 + 2] = f2tf(s4.z);
            skvp[d * SB + m0 + 3] = f2tf(s4.w);
        }
        if (tid < DD) sksp[tid] = g_ksp[(size_t)b * DD + tid];
    }
    __syncthreads();   // (A)

    // ---- phase 2: inter (all warps) + S units ----
    const int lr0 = (wid >> 1) * 16;       // local output row base (0..48)
    const int oc  = (wid & 1) * 32;        // output col base
    float cO[4][4];
    #pragma unroll
    for (int nj = 0; nj < 4; nj++)
        #pragma unroll
        for (int q = 0; q < 4; q++) cO[nj][q] = 0.f;

    // inter: phi(q)[lr0..+16] @ kvp -> cO, K=64
    #pragma unroll
    for (int kk = 0; kk < 8; kk++) {
        int kc = kk * 8 + tg;
        uint32_t a0 = __float_as_uint(sq[(lr0 + gid) * SB + kc]);
        uint32_t a1 = __float_as_uint(sq[(lr0 + 8 + gid) * SB + kc]);
        uint32_t a2 = __float_as_uint(sq[(lr0 + gid) * SB + kc + 4]);
        uint32_t a3 = __float_as_uint(sq[(lr0 + 8 + gid) * SB + kc + 4]);
        #pragma unroll
        for (int nj = 0; nj < 4; nj++) {
            uint32_t b0 = __float_as_uint(skvp[kc * SB + oc + nj * 8 + gid]);
            uint32_t b1 = __float_as_uint(skvp[(kc + 4) * SB + oc + nj * 8 + gid]);
            mma8(cO[nj], a0, a1, a2, a3, b0, b1);
        }
    }

    // S units: 16x32 causal blocks. lower: 14 units, upper: 6 units.
    {
        const int LGl[14] = {0,0,0,1,1,1,2,2,2,2,3,3,3,3};
        const int CGl[14] = {0,1,2,0,1,2,0,1,2,3,0,1,2,3};
        const int LGu[6]  = {0,1,2,2,3,3};
        const int CGu[6]  = {0,0,0,1,0,1};
        const int nu = half ? ((wid < 6) ? 2 : 1) : ((wid < 6) ? 1 : 0);

        #pragma unroll
        for (int t = 0; t < 2; t++) {
            if (t < nu) {
                int u = (t == 0) ? wid : wid + 8;
                int lgr = half ? LGl[u] : LGu[u];
                int cg  = half ? CGl[u] : CGu[u];
                int r0 = lgr * 16, c0g = cg * 32;
                float cT[4][4];
                #pragma unroll
                for (int nj = 0; nj < 4; nj++)
                    #pragma unroll
                    for (int q = 0; q < 4; q++) cT[nj][q] = 0.f;

                #pragma unroll
                for (int kk = 0; kk < 8; kk++) {
                    int kc = kk * 8 + tg;
                    uint32_t a0 = __float_as_uint(sq[(r0 + gid) * SB + kc]);
                    uint32_t a1 = __float_as_uint(sq[(r0 + 8 + gid) * SB + kc]);
                    uint32_t a2 = __float_as_uint(sq[(r0 + gid) * SB + kc + 4]);
                    uint32_t a3 = __float_as_uint(sq[(r0 + 8 + gid) * SB + kc + 4]);
                    #pragma unroll
                    for (int nj = 0; nj < 4; nj++) {
                        uint32_t b0 = __float_as_uint(skv[(c0g + nj * 8 + gid) * SB + kc]);
                        uint32_t b1 = __float_as_uint(skv[(c0g + nj * 8 + gid) * SB + kc + 4]);
                        mma8(cT[nj], a0, a1, a2, a3, b0, b1);
                    }
                }
                // mask (global col <= global row), rowsum partials, store tf32 S
                int rlo = r0 + gid, rhi = rlo + 8;
                int Rlo = half * 64 + rlo, Rhi = Rlo + 8;
                float zlo = 0.f, zhi = 0.f;
                #pragma unroll
                for (int nj = 0; nj < 4; nj++) {
                    int C0 = c0g + nj * 8 + 2 * tg, C1 = C0 + 1;
                    float s0 = (C0 <= Rlo) ? cT[nj][0] : 0.f;
                    float s1 = (C1 <= Rlo) ? cT[nj][1] : 0.f;
                    float s2 = (C0 <= Rhi) ? cT[nj][2] : 0.f;
                    float s3 = (C1 <= Rhi) ? cT[nj][3] : 0.f;
                    zlo += s0 + s1;
                    zhi += s2 + s3;
                    *(float2*)&sS[rlo * SSW + C0] = make_float2(f2tf(s0), f2tf(s1));
                    *(float2*)&sS[rhi * SSW + C0] = make_float2(f2tf(s2), f2tf(s3));
                }
                zlo += __shfl_xor_sync(0xffffffffu, zlo, 1);
                zlo += __shfl_xor_sync(0xffffffffu, zlo, 2);
                zhi += __shfl_xor_sync(0xffffffffu, zhi, 1);
                zhi += __shfl_xor_sync(0xffffffffu, zhi, 2);
                if (tg == 0) {
                    szp[cg * 64 + rlo] = zlo;
                    szp[cg * 64 + rhi] = zhi;
                }
            }
        }
    }
    __syncthreads();   // (B): S + szp done; skv(K) no longer read

    // ---- store V (tf32) into skv ----
    #pragma unroll
    for (int it = 0; it < 8; it++) {
        if (it < nk4it) {
            int idx = tid + it * 256;
            int r = idx >> 4, c0 = (idx & 15) * 4;
            skv[r * SB + c0 + 0] = f2tf(vreg[it].x);
            skv[r * SB + c0 + 1] = f2tf(vreg[it].y);
            skv[r * SB + c0 + 2] = f2tf(vreg[it].z);
            skv[r * SB + c0 + 3] = f2tf(vreg[it].w);
        }
    }
    __syncthreads();   // (C): V visible

    // ---- phase 3: z (threads 0-63) + intra ----
    if (tid < 64) {
        float qd = EPS;
        #pragma unroll 8
        for (int d = 0; d < DD; d++) qd += sq[tid * SB + d] * sksp[d];
        sz[tid] = qd + szp[tid] + szp[64 + tid] + szp[128 + tid] + szp[192 + tid];
    }

    {
        const int lgrg = half * 4 + (wid >> 1);   // global 16-row group
        const int nks = 2 * lgrg + 2;             // causally-trimmed K steps
        for (int kk = 0; kk < nks; kk++) {
            int kc = kk * 8 + tg;
            uint32_t a0 = __float_as_uint(sS[(lr0 + gid) * SSW + kc]);
            uint32_t a1 = __float_as_uint(sS[(lr0 + 8 + gid) * SSW + kc]);
            uint32_t a2 = __float_as_uint(sS[(lr0 + gid) * SSW + kc + 4]);
            uint32_t a3 = __float_as_uint(sS[(lr0 + 8 + gid) * SSW + kc + 4]);
            #pragma unroll
            for (int nj = 0; nj < 4; nj++) {
                uint32_t b0 = __float_as_uint(skv[kc * SB + oc + nj * 8 + gid]);
                uint32_t b1 = __float_as_uint(skv[(kc + 4) * SB + oc + nj * 8 + gid]);
                mma8(cO[nj], a0, a1, a2, a3, b0, b1);
            }
        }
    }
    __syncthreads();   // (D): sz visible

    // ---- epilogue ----
    {
        int rlo = lr0 + gid, rhi = rlo + 8;
        int Rlo = half * 64 + rlo, Rhi = Rlo + 8;
        float izlo = 1.f / sz[rlo], izhi = 1.f / sz[rhi];
        float* oblo = O + ((size_t)((n * LL + g * CC + Rlo) * HH + h)) * MM;
        float* obhi = O + ((size_t)((n * LL + g * CC + Rhi) * HH + h)) * MM;
        #pragma unroll
        for (int nj = 0; nj < 4; nj++) {
            int c0 = oc + nj * 8 + 2 * tg;
            *(float2*)(oblo + c0) = make_float2(cO[nj][0] * izlo, cO[nj][1] * izlo);
            *(float2*)(obhi + c0) = make_float2(cO[nj][2] * izhi, cO[nj][3] * izhi);
        }
    }
}

// ---------------------------------------------------------------------------
extern "C" void kernel_launch(void* const* d_in, const int* in_sizes, int n_in,
                              void* d_out, int out_size) {
    const float* Q = (const float*)d_in[0];
    const float* K = (const float*)d_in[1];
    const float* V = (const float*)d_in[2];
    float* O = (float*)d_out;

    cudaFuncSetAttribute(k_state, cudaFuncAttributeMaxDynamicSharedMemorySize, SMEM1);
    cudaFuncSetAttribute(k_main,  cudaFuncAttributeMaxDynamicSharedMemorySize, SMEM3);

    k_state<<<NTILE, 256, SMEM1>>>(K, V);
    k_scan<<<dim3(NB * HH, 4), 256>>>();
    k_main<<<NTILE * 2, 256, SMEM3>>>(Q, K, V, O);
}

// round 13
// speedup vs baseline: 1.1686x; 1.1686x over previous
#include <cuda_runtime.h>
#include <cstdint>

#define NB 4
#define LL 4096
#define HH 16
#define DD 64
#define MM 64
#define CC 128
#define GG 32
#define NTILE (NB*GG*HH)   // 2048
#define EPS 1e-6f

// k_main strides (floats) — R11 layout
#define SA 68
#define SB 72
#define SSW 132

__device__ float g_kv [NTILE*DD*MM];
__device__ float g_kvp[NTILE*DD*MM];
__device__ float g_ks [NTILE*DD];
__device__ float g_ksp[NTILE*DD];

__device__ __forceinline__ float phi(float x) { return x > 0.f ? x + 1.f : __expf(x); }
__device__ __forceinline__ float f2tf(float f) {
    uint32_t r; asm("cvt.rna.tf32.f32 %0, %1;" : "=r"(r) : "f"(f)); return __uint_as_float(r);
}
__device__ __forceinline__ void mma8(float c[4], uint32_t a0, uint32_t a1, uint32_t a2, uint32_t a3,
                                     uint32_t b0, uint32_t b1) {
    asm volatile("mma.sync.aligned.m16n8k8.row.col.f32.tf32.tf32.f32 "
                 "{%0,%1,%2,%3},{%4,%5,%6,%7},{%8,%9},{%0,%1,%2,%3};"
                 : "+f"(c[0]), "+f"(c[1]), "+f"(c[2]), "+f"(c[3])
                 : "r"(a0), "r"(a1), "r"(a2), "r"(a3), "r"(b0), "r"(b1));
}

// ---------------------------------------------------------------------------
// k_state with FRAGMENT-ORDERED smem.
//   A = phi(k)^T as 16x8 tiles (mt over d: 4, kt over c: 16), tile order kt*4+mt,
//       stride TA=136 fl; element addr = tile*TA + ((d&7)*4 + (c&3))*4
//                                       + ((c&7)>>2)*2 + ((d>>3)&1)
//   B = v as 8x8 tiles (nt over m: 8, kt over c: 16), order kt*8+nt, stride TB=66;
//       addr = tile*TB + ((m&7)*4 + (c&3))*2 + ((c>>2)&1)
//   Fragment reads: A = 1 x ld.shared.v4, B = 1 x ld.shared.v2 per tile.
// 256 threads, 3 CTAs/SM.
// ---------------------------------------------------------------------------
#define TA 136
#define TB 66
#define OFF_SB1 (64*TA)                 // 8704
#define OFF_RED (OFF_SB1 + 128*TB)      // 17152
#define SMEM1 ((OFF_RED + 256) * 4)     // 69632 bytes

__global__ __launch_bounds__(256, 3)
void k_state(const float* __restrict__ K, const float* __restrict__ V) {
    extern __shared__ float sm[];
    float* sA   = sm;
    float* sB   = sm + OFF_SB1;
    float* sred = sm + OFF_RED;
    const int tid = threadIdx.x, wid = tid >> 5, lane = tid & 31;
    const int gid = lane >> 2, tg = lane & 3;
    const int b = blockIdx.x, h = b & 15, g = (b >> 4) & 31, n = b >> 9;

    // ---- load + scatter to fragment order ----
    #pragma unroll
    for (int it = 0; it < 8; it++) {
        int idx = tid + it * 256;
        int c = idx >> 4, e0 = (idx & 15) * 4;
        int gb = ((n * LL + g * CC + c) * HH + h) * DD + e0;
        float4 k4 = *(const float4*)(K + gb);
        float4 v4 = *(const float4*)(V + gb);
        int kt = c >> 3, kc3 = c & 3, kcH = (c & 7) >> 2;
        // A (phi(k)); d = e0 + j
        int mt = e0 >> 4, dh = (e0 >> 3) & 1;
        int aB = (kt * 4 + mt) * TA + kc3 * 4 + kcH * 2 + dh + (e0 & 7) * 16;
        sA[aB +  0] = f2tf(phi(k4.x));
        sA[aB + 16] = f2tf(phi(k4.y));
        sA[aB + 32] = f2tf(phi(k4.z));
        sA[aB + 48] = f2tf(phi(k4.w));
        // B (v); m = e0 + j
        int nt = e0 >> 3;
        int bB = (kt * 8 + nt) * TB + kc3 * 2 + kcH + (e0 & 7) * 8;
        sB[bB +  0] = f2tf(v4.x);
        sB[bB +  8] = f2tf(v4.y);
        sB[bB + 16] = f2tf(v4.z);
        sB[bB + 24] = f2tf(v4.w);
    }
    __syncthreads();

    // ---- ksum partials: thread handles 32 c's of one d ----
    {
        int d = tid & 63, part = tid >> 6;
        int mt = d >> 4, dl = (d & 7) * 4, dh = (d >> 3) & 1;
        float s = 0.f;
        #pragma unroll 8
        for (int c = part * 32; c < part * 32 + 32; c++) {
            int addr = ((c >> 3) * 4 + mt) * TA + (dl + (c & 3)) * 4 + ((c & 7) >> 2) * 2 + dh;
            s += sA[addr];
        }
        sred[part * 64 + d] = s;
    }

    // ---- GEMM: warp tile rows d0..d0+15 (mt=wid>>1), cols oc..oc+31 (ntb), K=128 ----
    const int mt = wid >> 1, ntb = (wid & 1) * 4;
    float cD[4][4];
    #pragma unroll
    for (int nj = 0; nj < 4; nj++)
        #pragma unroll
        for (int q = 0; q < 4; q++) cD[nj][q] = 0.f;

    #pragma unroll
    for (int kk = 0; kk < 16; kk++) {
        float4 av = *(const float4*)&sA[(kk * 4 + mt) * TA + lane * 4];
        #pragma unroll
        for (int nj = 0; nj < 4; nj++) {
            float2 bv = *(const float2*)&sB[(kk * 8 + ntb + nj) * TB + lane * 2];
            mma8(cD[nj], __float_as_uint(av.x), __float_as_uint(av.y),
                         __float_as_uint(av.z), __float_as_uint(av.w),
                         __float_as_uint(bv.x), __float_as_uint(bv.y));
        }
    }

    const int d0 = mt * 16, oc = ntb * 8;
    float* dst = g_kv + (size_t)b * (DD * MM);
    #pragma unroll
    for (int nj = 0; nj < 4; nj++) {
        int col = oc + nj * 8 + 2 * tg;
        *(float2*)(dst + (d0 + gid) * MM + col)     = make_float2(cD[nj][0], cD[nj][1]);
        *(float2*)(dst + (d0 + 8 + gid) * MM + col) = make_float2(cD[nj][2], cD[nj][3]);
    }

    __syncthreads();
    if (tid < 64)
        g_ks[(size_t)b * DD + tid] = sred[tid] + sred[64 + tid] + sred[128 + tid] + sred[192 + tid];
}

// ---------------------------------------------------------------------------
// k_scan: exact R11 version. grid (64,4)x256.
// ---------------------------------------------------------------------------
__global__ __launch_bounds__(256, 4)
void k_scan() {
    const int nh = blockIdx.x, n = nh >> 4, h = nh & 15;
    const int pos = blockIdx.y * 1024 + threadIdx.x * 4;
    float4 acc = make_float4(0.f, 0.f, 0.f, 0.f);
    size_t base0 = ((size_t)(n * GG * HH + h)) * (DD * MM) + pos;
    float4 nxt = *(const float4*)&g_kv[base0];
    for (int g = 0; g < GG; g++) {
        float4 cur = nxt;
        size_t base = ((size_t)((n * GG + g) * HH + h)) * (DD * MM) + pos;
        if (g + 1 < GG) {
            size_t basen = ((size_t)((n * GG + g + 1) * HH + h)) * (DD * MM) + pos;
            nxt = *(const float4*)&g_kv[basen];
        }
        *(float4*)&g_kvp[base] = acc;
        acc.x += cur.x; acc.y += cur.y; acc.z += cur.z; acc.w += cur.w;
    }
    if (blockIdx.y == 0 && threadIdx.x < DD) {
        float a = 0.f;
        for (int g = 0; g < GG; g++) {
            size_t off = (size_t)((n * GG + g) * HH + h) * DD + threadIdx.x;
            g_ksp[off] = a;
            a += g_ks[off];
        }
    }
}

// ---------------------------------------------------------------------------
// k_main: exact R11 causal-trimmed version (best measured: ~141us).
// ---------------------------------------------------------------------------
#define OFF_SQ   0
#define OFF_SK   (CC*SA)
#define OFF_SV   (OFF_SK + CC*SA)
#define OFF_SS   (OFF_SV + CC*SB)
#define OFF_KVP  (OFF_SS + CC*SSW)
#define OFF_KSP  (OFF_KVP + DD*SB)
#define OFF_ZP   (OFF_KSP + DD)
#define OFF_Z    (OFF_ZP + 4*CC)
#define SM3_FLOATS (OFF_Z + CC)
#define SMEM3  (SM3_FLOATS * 4)

__global__ __launch_bounds__(512, 1)
void k_main(const float* __restrict__ Q, const float* __restrict__ K,
            const float* __restrict__ V, float* __restrict__ O) {
    extern __shared__ float sm[];
    float* sq   = sm + OFF_SQ;
    float* sk   = sm + OFF_SK;
    float* sv   = sm + OFF_SV;
    float* sS   = sm + OFF_SS;
    float* skvp = sm + OFF_KVP;
    float* sksp = sm + OFF_KSP;
    float* szp  = sm + OFF_ZP;
    float* sz   = sm + OFF_Z;

    const int tid = threadIdx.x, wid = tid >> 5, lane = tid & 31;
    const int gid = lane >> 2, tg = lane & 3;
    const int b = blockIdx.x, h = b & 15, g = (b >> 4) & 31, n = b >> 9;

    #pragma unroll
    for (int it = 0; it < 4; it++) {
        int idx = tid + it * 512;
        int r = idx >> 4, c0 = (idx & 15) * 4;
        int gb = ((n * LL + g * CC + r) * HH + h) * DD + c0;
        float4 q4 = *(const float4*)(Q + gb);
        float4 k4 = *(const float4*)(K + gb);
        float4 v4 = *(const float4*)(V + gb);
        sq[r * SA + c0 + 0] = f2tf(phi(q4.x));
        sq[r * SA + c0 + 1] = f2tf(phi(q4.y));
        sq[r * SA + c0 + 2] = f2tf(phi(q4.z));
        sq[r * SA + c0 + 3] = f2tf(phi(q4.w));
        sk[r * SA + c0 + 0] = f2tf(phi(k4.x));
        sk[r * SA + c0 + 1] = f2tf(phi(k4.y));
        sk[r * SA + c0 + 2] = f2tf(phi(k4.z));
        sk[r * SA + c0 + 3] = f2tf(phi(k4.w));
        sv[r * SB + c0 + 0] = f2tf(v4.x);
        sv[r * SB + c0 + 1] = f2tf(v4.y);
        sv[r * SB + c0 + 2] = f2tf(v4.z);
        sv[r * SB + c0 + 3] = f2tf(v4.w);
    }
    {
        const float* src = g_kvp + (size_t)b * (DD * MM);
        #pragma unroll
        for (int it = 0; it < 2; it++) {
            int idx = tid + it * 512;
            int d = idx >> 4, m0 = (idx & 15) * 4;
            float4 s4 = *(const float4*)(src + d * MM + m0);
            skvp[d * SB + m0 + 0] = f2tf(s4.x);
            skvp[d * SB + m0 + 1] = f2tf(s4.y);
            skvp[d * SB + m0 + 2] = f2tf(s4.z);
            skvp[d * SB + m0 + 3] = f2tf(s4.w);
        }
        if (tid < DD) sksp[tid] = g_ksp[(size_t)b * DD + tid];
    }
    __syncthreads();   // (A)

    const int widq = wid - 8;
    const int gra = widq >> 1, grb = 7 - gra;
    const int ra = gra * 16, rb = grb * 16;
    const int oc = (widq & 1) * 32;
    float cA[4][4], cB[4][4];

    if (wid < 4) {
        const int r0 = wid * 32, c0g = wid * 32;
        float cS[2][4][4];
        #pragma unroll
        for (int mi = 0; mi < 2; mi++)
            #pragma unroll
            for (int nj = 0; nj < 4; nj++)
                #pragma unroll
                for (int q = 0; q < 4; q++) cS[mi][nj][q] = 0.f;

        #pragma unroll
        for (int kk = 0; kk < 8; kk++) {
            int kc = kk * 8 + tg;
            uint32_t a[2][4];
            #pragma unroll
            for (int mi = 0; mi < 2; mi++) {
                int ar = r0 + mi * 16;
                a[mi][0] = __float_as_uint(sq[(ar + gid) * SA + kc]);
                a[mi][1] = __float_as_uint(sq[(ar + 8 + gid) * SA + kc]);
                a[mi][2] = __float_as_uint(sq[(ar + gid) * SA + kc + 4]);
                a[mi][3] = __float_as_uint(sq[(ar + 8 + gid) * SA + kc + 4]);
            }
            #pragma unroll
            for (int nj = 0; nj < 4; nj++) {
                uint32_t b0 = __float_as_uint(sk[(c0g + nj * 8 + gid) * SA + kc]);
                uint32_t b1 = __float_as_uint(sk[(c0g + nj * 8 + gid) * SA + kc + 4]);
                mma8(cS[0][nj], a[0][0], a[0][1], a[0][2], a[0][3], b0, b1);
                mma8(cS[1][nj], a[1][0], a[1][1], a[1][2], a[1][3], b0, b1);
            }
        }
        #pragma unroll
        for (int mi = 0; mi < 2; mi++) {
            int rlo = r0 + mi * 16 + gid, rhi = rlo + 8;
            float zlo = 0.f, zhi = 0.f;
            #pragma unroll
            for (int nj = 0; nj < 4; nj++) {
                int c0 = c0g + nj * 8 + 2 * tg, c1 = c0 + 1;
                float s0 = (c0 <= rlo) ? cS[mi][nj][0] : 0.f;
                float s1 = (c1 <= rlo) ? cS[mi][nj][1] : 0.f;
                float s2 = (c0 <= rhi) ? cS[mi][nj][2] : 0.f;
                float s3 = (c1 <= rhi) ? cS[mi][nj][3] : 0.f;
                zlo += s0 + s1;
                zhi += s2 + s3;
                *(float2*)&sS[rlo * SSW + c0] = make_float2(f2tf(s0), f2tf(s1));
                *(float2*)&sS[rhi * SSW + c0] = make_float2(f2tf(s2), f2tf(s3));
            }
            zlo += __shfl_xor_sync(0xffffffffu, zlo, 1);
            zlo += __shfl_xor_sync(0xffffffffu, zlo, 2);
            zhi += __shfl_xor_sync(0xffffffffu, zhi, 1);
            zhi += __shfl_xor_sync(0xffffffffu, zhi, 2);
            if (tg == 0) {
                szp[wid * CC + rlo] = zlo;
                szp[wid * CC + rhi] = zhi;
            }
        }
    } else if (wid < 8) {
        const int w = wid - 4;
        const int GRt[4][3] = {{2,4,6},{3,5,7},{4,5,6},{7,6,7}};
        const int CGt[4][3] = {{0,0,0},{0,0,0},{1,1,1},{1,2,2}};
        #pragma unroll
        for (int t = 0; t < 3; t++) {
            const int gr = GRt[w][t], cg = CGt[w][t];
            const int r0 = gr * 16, c0g = cg * 32;
            float cT[4][4];
            #pragma unroll
            for (int nj = 0; nj < 4; nj++)
                #pragma unroll
                for (int q = 0; q < 4; q++) cT[nj][q] = 0.f;

            #pragma unroll
            for (int kk = 0; kk < 8; kk++) {
                int kc = kk * 8 + tg;
                uint32_t a0 = __float_as_uint(sq[(r0 + gid) * SA + kc]);
                uint32_t a1 = __float_as_uint(sq[(r0 + 8 + gid) * SA + kc]);
                uint32_t a2 = __float_as_uint(sq[(r0 + gid) * SA + kc + 4]);
                uint32_t a3 = __float_as_uint(sq[(r0 + 8 + gid) * SA + kc + 4]);
                #pragma unroll
                for (int nj = 0; nj < 4; nj++) {
                    uint32_t b0 = __float_as_uint(sk[(c0g + nj * 8 + gid) * SA + kc]);
                    uint32_t b1 = __float_as_uint(sk[(c0g + nj * 8 + gid) * SA + kc + 4]);
                    mma8(cT[nj], a0, a1, a2, a3, b0, b1);
                }
            }
            int rlo = r0 + gid, rhi = rlo + 8;
            float zlo = 0.f, zhi = 0.f;
            #pragma unroll
            for (int nj = 0; nj < 4; nj++) {
                int c0 = c0g + nj * 8 + 2 * tg;
                zlo += cT[nj][0] + cT[nj][1];
                zhi += cT[nj][2] + cT[nj][3];
                *(float2*)&sS[rlo * SSW + c0] = make_float2(f2tf(cT[nj][0]), f2tf(cT[nj][1]));
                *(float2*)&sS[rhi * SSW + c0] = make_float2(f2tf(cT[nj][2]), f2tf(cT[nj][3]));
            }
            zlo += __shfl_xor_sync(0xffffffffu, zlo, 1);
            zlo += __shfl_xor_sync(0xffffffffu, zlo, 2);
            zhi += __shfl_xor_sync(0xffffffffu, zhi, 1);
            zhi += __shfl_xor_sync(0xffffffffu, zhi, 2);
            if (tg == 0) {
                szp[cg * CC + rlo] = zlo;
                szp[cg * CC + rhi] = zhi;
            }
        }
    } else {
        #pragma unroll
        for (int nj = 0; nj < 4; nj++)
            #pragma unroll
            for (int q = 0; q < 4; q++) { cA[nj][q] = 0.f; cB[nj][q] = 0.f; }

        #pragma unroll
        for (int kk = 0; kk < 8; kk++) {
            int kc = kk * 8 + tg;
            uint32_t aA0 = __float_as_uint(sq[(ra + gid) * SA + kc]);
            uint32_t aA1 = __float_as_uint(sq[(ra + 8 + gid) * SA + kc]);
            uint32_t aA2 = __float_as_uint(sq[(ra + gid) * SA + kc + 4]);
            uint32_t aA3 = __float_as_uint(sq[(ra + 8 + gid) * SA + kc + 4]);
            uint32_t aB0 = __float_as_uint(sq[(rb + gid) * SA + kc]);
            uint32_t aB1 = __float_as_uint(sq[(rb + 8 + gid) * SA + kc]);
            uint32_t aB2 = __float_as_uint(sq[(rb + gid) * SA + kc + 4]);
            uint32_t aB3 = __float_as_uint(sq[(rb + 8 + gid) * SA + kc + 4]);
            #pragma unroll
            for (int nj = 0; nj < 4; nj++) {
                uint32_t b0 = __float_as_uint(skvp[kc * SB + oc + nj * 8 + gid]);
                uint32_t b1 = __float_as_uint(skvp[(kc + 4) * SB + oc + nj * 8 + gid]);
                mma8(cA[nj], aA0, aA1, aA2, aA3, b0, b1);
                mma8(cB[nj], aB0, aB1, aB2, aB3, b0, b1);
            }
        }
    }
    __syncthreads();   // (B)

    if (wid < 8) {
        if (tid < CC) {
            int r = tid, rg = r >> 5;
            float qd = EPS;
            #pragma unroll 8
            for (int d = 0; d < DD; d++) qd += sq[r * SA + d] * sksp[d];
            float s = szp[r];
            if (rg >= 1) s += szp[CC + r];
            if (rg >= 2) s += szp[2 * CC + r];
            if (rg >= 3) s += szp[3 * CC + r];
            sz[r] = qd + s;
        }
    } else {
        const int nka = 2 * gra + 2, nkb = 2 * grb + 2;
        for (int kk = 0; kk < nka; kk++) {
            int kc = kk * 8 + tg;
            uint32_t a0 = __float_as_uint(sS[(ra + gid) * SSW + kc]);
            uint32_t a1 = __float_as_uint(sS[(ra + 8 + gid) * SSW + kc]);
            uint32_t a2 = __float_as_uint(sS[(ra + gid) * SSW + kc + 4]);
            uint32_t a3 = __float_as_uint(sS[(ra + 8 + gid) * SSW + kc + 4]);
            #pragma unroll
            for (int nj = 0; nj < 4; nj++) {
                uint32_t b0 = __float_as_uint(sv[kc * SB + oc + nj * 8 + gid]);
                uint32_t b1 = __float_as_uint(sv[(kc + 4) * SB + oc + nj * 8 + gid]);
                mma8(cA[nj], a0, a1, a2, a3, b0, b1);
            }
        }
        for (int kk = 0; kk < nkb; kk++) {
            int kc = kk * 8 + tg;
            uint32_t a0 = __float_as_uint(sS[(rb + gid) * SSW + kc]);
            uint32_t a1 = __float_as_uint(sS[(rb + 8 + gid) * SSW + kc]);
            uint32_t a2 = __float_as_uint(sS[(rb + gid) * SSW + kc + 4]);
            uint32_t a3 = __float_as_uint(sS[(rb + 8 + gid) * SSW + kc + 4]);
            #pragma unroll
            for (int nj = 0; nj < 4; nj++) {
                uint32_t b0 = __float_as_uint(sv[kc * SB + oc + nj * 8 + gid]);
                uint32_t b1 = __float_as_uint(sv[(kc + 4) * SB + oc + nj * 8 + gid]);
                mma8(cB[nj], a0, a1, a2, a3, b0, b1);
            }
        }
    }
    __syncthreads();   // (C)

    if (wid >= 8) {
        int rlo = ra + gid, rhi = rlo + 8;
        float izlo = 1.f / sz[rlo], izhi = 1.f / sz[rhi];
        float* oblo = O + ((size_t)((n * LL + g * CC + rlo) * HH + h)) * MM;
        float* obhi = O + ((size_t)((n * LL + g * CC + rhi) * HH + h)) * MM;
        #pragma unroll
        for (int nj = 0; nj < 4; nj++) {
            int c0 = oc + nj * 8 + 2 * tg;
            *(float2*)(oblo + c0) = make_float2(cA[nj][0] * izlo, cA[nj][1] * izlo);
            *(float2*)(obhi + c0) = make_float2(cA[nj][2] * izhi, cA[nj][3] * izhi);
        }
        rlo = rb + gid; rhi = rlo + 8;
        izlo = 1.f / sz[rlo]; izhi = 1.f / sz[rhi];
        oblo = O + ((size_t)((n * LL + g * CC + rlo) * HH + h)) * MM;
        obhi = O + ((size_t)((n * LL + g * CC + rhi) * HH + h)) * MM;
        #pragma unroll
        for (int nj = 0; nj < 4; nj++) {
            int c0 = oc + nj * 8 + 2 * tg;
            *(float2*)(oblo + c0) = make_float2(cB[nj][0] * izlo, cB[nj][1] * izlo);
            *(float2*)(obhi + c0) = make_float2(cB[nj][2] * izhi, cB[nj][3] * izhi);
        }
    }
}

// ---------------------------------------------------------------------------
extern "C" void kernel_launch(void* const* d_in, const int* in_sizes, int n_in,
                              void* d_out, int out_size) {
    const float* Q = (const float*)d_in[0];
    const float* K = (const float*)d_in[1];
    const float* V = (const float*)d_in[2];
    float* O = (float*)d_out;

    cudaFuncSetAttribute(k_state, cudaFuncAttributeMaxDynamicSharedMemorySize, SMEM1);
    cudaFuncSetAttribute(k_main,  cudaFuncAttributeMaxDynamicSharedMemorySize, SMEM3);

    k_state<<<NTILE, 256, SMEM1>>>(K, V);
    k_scan<<<dim3(NB * HH, 4), 256>>>();
    k_main<<<NTILE, 512, SMEM3>>>(Q, K, V, O);
}